// round 1
// baseline (speedup 1.0000x reference)
#include <cuda_runtime.h>
#include <math.h>

#define NN 100000
#define EE 1600000
#define IND 256
#define OUTD 128

// ---------------- scratch (static device globals; no allocation) ----------------
__device__ __align__(16) float g_seq[(size_t)NN * OUTD];   // seq_fts = feat @ W
__device__ float g_f1[NN];
__device__ float g_f2[NN];
__device__ int   g_cnt[NN];          // histogram, then reused as scatter cursor
__device__ int   g_rowptr[NN + 1];   // CSR row pointers (by destination `row`)
__device__ int   g_ccol[EE];         // CSR col indices
__device__ float g_elog[EE];         // CSR-ordered leaky_relu logits

// ---------------- GEMM: g_seq = feat[N,256] @ W[256,128] (fp32 SIMT) ----------------
__global__ __launch_bounds__(256) void gemm_kernel(const float* __restrict__ A,
                                                   const float* __restrict__ B) {
    __shared__ float As[16][128];   // transposed A tile: As[k][m]
    __shared__ float Bs[16][128];   // Bs[k][n]
    const int tid = threadIdx.x;
    const int m0  = blockIdx.x * 128;
    const int tx  = tid & 15, ty = tid >> 4;

    float acc[8][8];
#pragma unroll
    for (int i = 0; i < 8; i++)
#pragma unroll
        for (int j = 0; j < 8; j++) acc[i][j] = 0.f;

    for (int k0 = 0; k0 < IND; k0 += 16) {
        // load A tile: 128 rows x 16 k  (512 float4, 2 per thread)
#pragma unroll
        for (int i = 0; i < 2; i++) {
            int idx = tid + i * 256;
            int r = idx >> 2, kq = idx & 3;
            int gr = m0 + r;
            float4 v = make_float4(0.f, 0.f, 0.f, 0.f);
            if (gr < NN) v = *(const float4*)(A + (size_t)gr * IND + k0 + kq * 4);
            As[kq * 4 + 0][r] = v.x;
            As[kq * 4 + 1][r] = v.y;
            As[kq * 4 + 2][r] = v.z;
            As[kq * 4 + 3][r] = v.w;
        }
        // load B tile: 16 k x 128 n
#pragma unroll
        for (int i = 0; i < 2; i++) {
            int idx = tid + i * 256;
            int r = idx >> 5, cq = idx & 31;
            *(float4*)&Bs[r][cq * 4] = *(const float4*)(B + (size_t)(k0 + r) * OUTD + cq * 4);
        }
        __syncthreads();
#pragma unroll
        for (int k = 0; k < 16; k++) {
            float4 a0 = *(const float4*)&As[k][ty * 8];
            float4 a1 = *(const float4*)&As[k][ty * 8 + 4];
            float4 b0 = *(const float4*)&Bs[k][tx * 8];
            float4 b1 = *(const float4*)&Bs[k][tx * 8 + 4];
            float ra[8] = {a0.x, a0.y, a0.z, a0.w, a1.x, a1.y, a1.z, a1.w};
            float rb[8] = {b0.x, b0.y, b0.z, b0.w, b1.x, b1.y, b1.z, b1.w};
#pragma unroll
            for (int i = 0; i < 8; i++)
#pragma unroll
                for (int j = 0; j < 8; j++) acc[i][j] = fmaf(ra[i], rb[j], acc[i][j]);
        }
        __syncthreads();
    }
#pragma unroll
    for (int i = 0; i < 8; i++) {
        int gr = m0 + ty * 8 + i;
        if (gr < NN) {
            float* o = g_seq + (size_t)gr * OUTD + tx * 8;
            *(float4*)o       = make_float4(acc[i][0], acc[i][1], acc[i][2], acc[i][3]);
            *(float4*)(o + 4) = make_float4(acc[i][4], acc[i][5], acc[i][6], acc[i][7]);
        }
    }
}

// ---------------- f1/f2 projections: warp per node ----------------
__global__ __launch_bounds__(256) void f12_kernel(const float* __restrict__ a_l,
                                                  const float* __restrict__ b_l,
                                                  const float* __restrict__ a_r,
                                                  const float* __restrict__ b_r) {
    int warp = (blockIdx.x * blockDim.x + threadIdx.x) >> 5;
    int lane = threadIdx.x & 31;
    if (warp >= NN) return;
    float4 v  = *(const float4*)(g_seq + (size_t)warp * OUTD + lane * 4);
    float4 al = *(const float4*)(a_l + lane * 4);
    float4 ar = *(const float4*)(a_r + lane * 4);
    float s1 = v.x * al.x + v.y * al.y + v.z * al.z + v.w * al.w;
    float s2 = v.x * ar.x + v.y * ar.y + v.z * ar.z + v.w * ar.w;
#pragma unroll
    for (int o = 16; o; o >>= 1) {
        s1 += __shfl_xor_sync(0xffffffffu, s1, o);
        s2 += __shfl_xor_sync(0xffffffffu, s2, o);
    }
    if (lane == 0) {
        g_f1[warp] = s1 + *b_l;
        g_f2[warp] = s2 + *b_r;
    }
}

// ---------------- CSR build ----------------
__global__ void zero_cnt_kernel() {
    int i = blockIdx.x * blockDim.x + threadIdx.x;
    if (i < NN) g_cnt[i] = 0;
}

__global__ void hist_kernel(const int* __restrict__ row) {
    int e = blockIdx.x * blockDim.x + threadIdx.x;
    if (e < EE) atomicAdd(&g_cnt[row[e]], 1);
}

// single block, 1024 threads: exclusive scan of g_cnt -> g_rowptr, zero g_cnt
__global__ __launch_bounds__(1024) void scan_kernel() {
    __shared__ int wsum[32];
    __shared__ int chunk_off;
    const int t = threadIdx.x;
    const int lane = t & 31, wid = t >> 5;
    if (t == 0) { chunk_off = 0; g_rowptr[0] = 0; }
    __syncthreads();
    for (int base = 0; base < NN; base += 1024) {
        int i = base + t;
        int v = (i < NN) ? g_cnt[i] : 0;
        if (i < NN) g_cnt[i] = 0;
        int x = v;
#pragma unroll
        for (int o = 1; o < 32; o <<= 1) {
            int y = __shfl_up_sync(0xffffffffu, x, o);
            if (lane >= o) x += y;
        }
        if (lane == 31) wsum[wid] = x;
        __syncthreads();
        if (wid == 0) {
            int w = wsum[lane];
#pragma unroll
            for (int o = 1; o < 32; o <<= 1) {
                int y = __shfl_up_sync(0xffffffffu, w, o);
                if (lane >= o) w += y;
            }
            wsum[lane] = w;
        }
        __syncthreads();
        int basew = (wid > 0) ? wsum[wid - 1] : 0;
        int incl = chunk_off + basew + x;
        if (i < NN) g_rowptr[i + 1] = incl;
        __syncthreads();
        if (t == 1023) chunk_off = incl;
        __syncthreads();
    }
}

__global__ void scatter_kernel(const int* __restrict__ row, const int* __restrict__ col) {
    int e = blockIdx.x * blockDim.x + threadIdx.x;
    if (e >= EE) return;
    int r = row[e], c = col[e];
    int pos = g_rowptr[r] + atomicAdd(&g_cnt[r], 1);
    g_ccol[pos] = c;
    float x = g_f1[r] + g_f2[c];
    g_elog[pos] = (x > 0.f) ? x : 0.2f * x;   // leaky_relu(0.2)
}

// ---------------- fused segment softmax + weighted gather: warp per row ----------------
__global__ __launch_bounds__(256) void row_kernel(const float* __restrict__ bias,
                                                  float* __restrict__ out) {
    int warp = (blockIdx.x * blockDim.x + threadIdx.x) >> 5;
    int lane = threadIdx.x & 31;
    if (warp >= NN) return;
    const int start = g_rowptr[warp];
    const int end   = g_rowptr[warp + 1];

    // pass 1: max
    float m = -INFINITY;
    for (int k = start + lane; k < end; k += 32) m = fmaxf(m, g_elog[k]);
#pragma unroll
    for (int o = 16; o; o >>= 1) m = fmaxf(m, __shfl_xor_sync(0xffffffffu, m, o));

    // pass 2: sum of exp
    float s = 0.f;
    for (int k = start + lane; k < end; k += 32) s += __expf(g_elog[k] - m);
#pragma unroll
    for (int o = 16; o; o >>= 1) s += __shfl_xor_sync(0xffffffffu, s, o);
    float inv = (s > 0.f) ? (1.f / s) : 0.f;

    // pass 3: weighted gather — each lane owns 4 output features
    float4 acc = make_float4(0.f, 0.f, 0.f, 0.f);
    for (int k = start; k < end; k++) {
        float c = __expf(g_elog[k] - m) * inv;   // broadcast load + same-value MUFU in all lanes
        int j = g_ccol[k];
        float4 v = *(const float4*)(g_seq + (size_t)j * OUTD + lane * 4);
        acc.x = fmaf(c, v.x, acc.x);
        acc.y = fmaf(c, v.y, acc.y);
        acc.z = fmaf(c, v.z, acc.z);
        acc.w = fmaf(c, v.w, acc.w);
    }

    float4 b = *(const float4*)(bias + lane * 4);
    acc.x += b.x; acc.y += b.y; acc.z += b.z; acc.w += b.w;
    // elu (alpha=1)
    acc.x = (acc.x > 0.f) ? acc.x : expm1f(acc.x);
    acc.y = (acc.y > 0.f) ? acc.y : expm1f(acc.y);
    acc.z = (acc.z > 0.f) ? acc.z : expm1f(acc.z);
    acc.w = (acc.w > 0.f) ? acc.w : expm1f(acc.w);
    *(float4*)(out + (size_t)warp * OUTD + lane * 4) = acc;
}

// ---------------- launch ----------------
extern "C" void kernel_launch(void* const* d_in, const int* in_sizes, int n_in,
                              void* d_out, int out_size) {
    const float* feat = (const float*)d_in[0];
    const float* W    = (const float*)d_in[1];
    const float* a_l  = (const float*)d_in[2];
    const float* b_l  = (const float*)d_in[3];
    const float* a_r  = (const float*)d_in[4];
    const float* b_r  = (const float*)d_in[5];
    const float* bias = (const float*)d_in[6];
    const int*   row  = (const int*)d_in[7];
    const int*   col  = (const int*)d_in[8];
    float* out = (float*)d_out;
    (void)in_sizes; (void)n_in; (void)out_size;

    zero_cnt_kernel<<<(NN + 255) / 256, 256>>>();
    gemm_kernel<<<(NN + 127) / 128, 256>>>(feat, W);
    f12_kernel<<<(NN + 7) / 8, 256>>>(a_l, b_l, a_r, b_r);
    hist_kernel<<<(EE + 255) / 256, 256>>>(row);
    scan_kernel<<<1, 1024>>>();
    scatter_kernel<<<(EE + 255) / 256, 256>>>(row, col);
    row_kernel<<<(NN + 7) / 8, 256>>>(bias, out);
}

// round 4
// speedup vs baseline: 1.6565x; 1.6565x over previous
#include <cuda_runtime.h>
#include <cuda_bf16.h>
#include <math.h>
#include <stdint.h>

#define NN 100000
#define EE 1600000
#define IND 256
#define OUTD 128
#define KP 40   // smem k-stride (bf16 elems): 80B rows -> conflict-free frags, 16B-aligned

// ---------------- scratch (static device globals; no allocation) ----------------
__device__ __align__(16) float g_seq[(size_t)NN * OUTD];   // seq_fts = feat @ W
__device__ float g_f1[NN];
__device__ float g_f2[NN];
__device__ int   g_cnt[NN];          // histogram, then reused as scatter cursor
__device__ int   g_rowptr[NN + 1];   // CSR row pointers (by destination `row`)
__device__ int   g_ccol[EE];         // CSR col indices
__device__ float g_elog[EE];         // CSR-ordered leaky_relu logits
__device__ int   g_locs[NN];         // per-element block-local inclusive scan
__device__ int   g_bsum[128];        // per-block sums
__device__ int   g_boff[128];        // per-block exclusive offsets
__device__ __align__(16) __nv_bfloat16 g_wt_hi[OUTD * IND];  // W^T split hi  [n][k]
__device__ __align__(16) __nv_bfloat16 g_wt_lo[OUTD * IND];  // W^T split lo  [n][k]

// ---------------- helpers ----------------
__device__ __forceinline__ void mma16816(float* c, const uint32_t* a, uint32_t b0, uint32_t b1) {
    asm volatile(
        "mma.sync.aligned.m16n8k16.row.col.f32.bf16.bf16.f32 "
        "{%0,%1,%2,%3},{%4,%5,%6,%7},{%8,%9},{%0,%1,%2,%3};"
        : "+f"(c[0]), "+f"(c[1]), "+f"(c[2]), "+f"(c[3])
        : "r"(a[0]), "r"(a[1]), "r"(a[2]), "r"(a[3]), "r"(b0), "r"(b1));
}

__device__ __forceinline__ void split1(float x, __nv_bfloat16& hi, __nv_bfloat16& lo) {
    hi = __float2bfloat16(x);
    lo = __float2bfloat16(x - __bfloat162float(hi));
}

// ---------------- prep: W[k][n] -> Wt_hi/lo[n][k] (bf16 split) ----------------
__global__ void prep_w_kernel(const float* __restrict__ W) {
    int idx = blockIdx.x * blockDim.x + threadIdx.x;   // 32768
    if (idx >= IND * OUTD) return;
    int k = idx & (IND - 1);
    int n = idx >> 8;
    float v = W[(size_t)k * OUTD + n];
    __nv_bfloat16 hi, lo;
    split1(v, hi, lo);
    g_wt_hi[(size_t)n * IND + k] = hi;
    g_wt_lo[(size_t)n * IND + k] = lo;
}

// ---------------- GEMM: g_seq = feat[N,256] @ W[256,128], split-bf16 mma ----------------
// block: 128 rows x 128 cols, 256 threads (8 warps, 4x2 warp grid), BK=32.
__global__ __launch_bounds__(256) void gemm_kernel(const float* __restrict__ A) {
    __shared__ __nv_bfloat16 As_hi[128][KP];
    __shared__ __nv_bfloat16 As_lo[128][KP];
    __shared__ __nv_bfloat16 Bs_hi[128][KP];
    __shared__ __nv_bfloat16 Bs_lo[128][KP];

    const int tid  = threadIdx.x;
    const int lane = tid & 31;
    const int wid  = tid >> 5;
    const int g    = lane >> 2;       // group id
    const int tg   = lane & 3;        // thread-in-group
    const int m0   = blockIdx.x * 128;
    const int mb   = (wid & 3) * 32;  // warp m base within block
    const int nb   = (wid >> 2) * 64; // warp n base

    float acc[2][8][4];
#pragma unroll
    for (int mt = 0; mt < 2; mt++)
#pragma unroll
        for (int nt = 0; nt < 8; nt++)
#pragma unroll
            for (int i = 0; i < 4; i++) acc[mt][nt][i] = 0.f;

    // staging registers
    float4 aReg[4];
    uint4  bHi[2], bLo[2];

    auto load_tile = [&](int it) {
        const int k0 = it * 32;
#pragma unroll
        for (int p = 0; p < 4; p++) {
            int idx = p * 256 + tid;
            int r = idx >> 3, kg = idx & 7;
            int gr = m0 + r;
            aReg[p] = (gr < NN) ? *(const float4*)(A + (size_t)gr * IND + k0 + kg * 4)
                                : make_float4(0.f, 0.f, 0.f, 0.f);
        }
#pragma unroll
        for (int p = 0; p < 2; p++) {
            int idx = p * 256 + tid;
            int n = idx >> 2, kg = idx & 3;   // kg*8 bf16 = 16B
            bHi[p] = *(const uint4*)(g_wt_hi + (size_t)n * IND + k0 + kg * 8);
            bLo[p] = *(const uint4*)(g_wt_lo + (size_t)n * IND + k0 + kg * 8);
        }
    };

    auto store_tile = [&]() {
#pragma unroll
        for (int p = 0; p < 4; p++) {
            int idx = p * 256 + tid;
            int r = idx >> 3, kg = idx & 7;
            __nv_bfloat162 h01, h23, l01, l23;
            split1(aReg[p].x, h01.x, l01.x);
            split1(aReg[p].y, h01.y, l01.y);
            split1(aReg[p].z, h23.x, l23.x);
            split1(aReg[p].w, h23.y, l23.y);
            *(__nv_bfloat162*)&As_hi[r][kg * 4]     = h01;
            *(__nv_bfloat162*)&As_hi[r][kg * 4 + 2] = h23;
            *(__nv_bfloat162*)&As_lo[r][kg * 4]     = l01;
            *(__nv_bfloat162*)&As_lo[r][kg * 4 + 2] = l23;
        }
#pragma unroll
        for (int p = 0; p < 2; p++) {
            int idx = p * 256 + tid;
            int n = idx >> 2, kg = idx & 3;
            *(uint4*)&Bs_hi[n][kg * 8] = bHi[p];
            *(uint4*)&Bs_lo[n][kg * 8] = bLo[p];
        }
    };

    auto compute = [&]() {
#pragma unroll
        for (int ks = 0; ks < 32; ks += 16) {
            uint32_t ah[2][4], al[2][4];
#pragma unroll
            for (int mt = 0; mt < 2; mt++) {
                const __nv_bfloat16* p = &As_hi[mb + mt * 16 + g][ks + tg * 2];
                ah[mt][0] = *(const uint32_t*)p;
                ah[mt][1] = *(const uint32_t*)(p + 8 * KP);
                ah[mt][2] = *(const uint32_t*)(p + 8);
                ah[mt][3] = *(const uint32_t*)(p + 8 * KP + 8);
                const __nv_bfloat16* q = &As_lo[mb + mt * 16 + g][ks + tg * 2];
                al[mt][0] = *(const uint32_t*)q;
                al[mt][1] = *(const uint32_t*)(q + 8 * KP);
                al[mt][2] = *(const uint32_t*)(q + 8);
                al[mt][3] = *(const uint32_t*)(q + 8 * KP + 8);
            }
#pragma unroll
            for (int nt = 0; nt < 8; nt++) {
                const __nv_bfloat16* pb = &Bs_hi[nb + nt * 8 + g][ks + tg * 2];
                uint32_t bh0 = *(const uint32_t*)pb;
                uint32_t bh1 = *(const uint32_t*)(pb + 8);
                const __nv_bfloat16* pl = &Bs_lo[nb + nt * 8 + g][ks + tg * 2];
                uint32_t bl0 = *(const uint32_t*)pl;
                uint32_t bl1 = *(const uint32_t*)(pl + 8);
#pragma unroll
                for (int mt = 0; mt < 2; mt++) {
                    mma16816(acc[mt][nt], ah[mt], bh0, bh1);
                    mma16816(acc[mt][nt], ah[mt], bl0, bl1);
                    mma16816(acc[mt][nt], al[mt], bh0, bh1);
                }
            }
        }
    };

    load_tile(0);
    store_tile();
    __syncthreads();
#pragma unroll 1
    for (int it = 0; it < 8; it++) {
        if (it < 7) load_tile(it + 1);
        compute();
        __syncthreads();
        if (it < 7) {
            store_tile();
            __syncthreads();
        }
    }

    // epilogue: write fp32 result
#pragma unroll
    for (int mt = 0; mt < 2; mt++) {
        int r0 = m0 + mb + mt * 16 + g;
        int r1 = r0 + 8;
#pragma unroll
        for (int nt = 0; nt < 8; nt++) {
            int c = nb + nt * 8 + tg * 2;
            if (r0 < NN) *(float2*)&g_seq[(size_t)r0 * OUTD + c] = make_float2(acc[mt][nt][0], acc[mt][nt][1]);
            if (r1 < NN) *(float2*)&g_seq[(size_t)r1 * OUTD + c] = make_float2(acc[mt][nt][2], acc[mt][nt][3]);
        }
    }
}

// ---------------- f1/f2 projections: warp per node ----------------
__global__ __launch_bounds__(256) void f12_kernel(const float* __restrict__ a_l,
                                                  const float* __restrict__ b_l,
                                                  const float* __restrict__ a_r,
                                                  const float* __restrict__ b_r) {
    int warp = (blockIdx.x * blockDim.x + threadIdx.x) >> 5;
    int lane = threadIdx.x & 31;
    if (warp >= NN) return;
    float4 v  = *(const float4*)(g_seq + (size_t)warp * OUTD + lane * 4);
    float4 al = *(const float4*)(a_l + lane * 4);
    float4 ar = *(const float4*)(a_r + lane * 4);
    float s1 = v.x * al.x + v.y * al.y + v.z * al.z + v.w * al.w;
    float s2 = v.x * ar.x + v.y * ar.y + v.z * ar.z + v.w * ar.w;
#pragma unroll
    for (int o = 16; o; o >>= 1) {
        s1 += __shfl_xor_sync(0xffffffffu, s1, o);
        s2 += __shfl_xor_sync(0xffffffffu, s2, o);
    }
    if (lane == 0) {
        g_f1[warp] = s1 + *b_l;
        g_f2[warp] = s2 + *b_r;
    }
}

// ---------------- CSR build ----------------
__global__ void zero_cnt_kernel() {
    int i = blockIdx.x * blockDim.x + threadIdx.x;
    if (i < NN) g_cnt[i] = 0;
}

__global__ void hist_kernel(const int* __restrict__ row) {
    int e = blockIdx.x * blockDim.x + threadIdx.x;
    if (e < EE) atomicAdd(&g_cnt[row[e]], 1);
}

// parallel scan, stage A: per-block inclusive scan of g_cnt (also zeroes g_cnt)
__global__ __launch_bounds__(1024) void scanA_kernel() {
    __shared__ int wsum[32];
    const int t = threadIdx.x;
    const int lane = t & 31, wid = t >> 5;
    int i = blockIdx.x * 1024 + t;
    int v = (i < NN) ? g_cnt[i] : 0;
    if (i < NN) g_cnt[i] = 0;
    int x = v;
#pragma unroll
    for (int o = 1; o < 32; o <<= 1) {
        int y = __shfl_up_sync(0xffffffffu, x, o);
        if (lane >= o) x += y;
    }
    if (lane == 31) wsum[wid] = x;
    __syncthreads();
    if (wid == 0) {
        int w = wsum[lane];
#pragma unroll
        for (int o = 1; o < 32; o <<= 1) {
            int y = __shfl_up_sync(0xffffffffu, w, o);
            if (lane >= o) w += y;
        }
        wsum[lane] = w;
    }
    __syncthreads();
    int incl = x + ((wid > 0) ? wsum[wid - 1] : 0);
    if (i < NN) g_locs[i] = incl;
    if (t == 1023) g_bsum[blockIdx.x] = incl;
}

// stage B: exclusive scan of 98 block sums (single small block)
__global__ __launch_bounds__(128) void scanB_kernel() {
    const int t = threadIdx.x;
    const int lane = t & 31, wid = t >> 5;
    __shared__ int ws[4];
    int v = (t < 98) ? g_bsum[t] : 0;
    int x = v;
#pragma unroll
    for (int o = 1; o < 32; o <<= 1) {
        int y = __shfl_up_sync(0xffffffffu, x, o);
        if (lane >= o) x += y;
    }
    if (lane == 31) ws[wid] = x;
    __syncthreads();
    if (t == 0) {
        int s = 0;
#pragma unroll
        for (int i = 0; i < 4; i++) { int tmp = ws[i]; ws[i] = s; s += tmp; }
    }
    __syncthreads();
    int incl = x + ws[wid];
    if (t < 98) g_boff[t] = incl - v;
    if (t == 0) g_rowptr[0] = 0;
}

// stage C: combine
__global__ __launch_bounds__(1024) void scanC_kernel() {
    int i = blockIdx.x * 1024 + threadIdx.x;
    if (i < NN) g_rowptr[i + 1] = g_locs[i] + g_boff[i >> 10];
}

__global__ void scatter_kernel(const int* __restrict__ row, const int* __restrict__ col) {
    int e = blockIdx.x * blockDim.x + threadIdx.x;
    if (e >= EE) return;
    int r = row[e], c = col[e];
    int pos = g_rowptr[r] + atomicAdd(&g_cnt[r], 1);
    g_ccol[pos] = c;
    float x = g_f1[r] + g_f2[c];
    g_elog[pos] = (x > 0.f) ? x : 0.2f * x;   // leaky_relu(0.2)
}

// ---------------- fused segment softmax + weighted gather: warp per row ----------------
__global__ __launch_bounds__(256) void row_kernel(const float* __restrict__ bias,
                                                  float* __restrict__ out) {
    int warp = (blockIdx.x * blockDim.x + threadIdx.x) >> 5;
    int lane = threadIdx.x & 31;
    if (warp >= NN) return;
    const int start = g_rowptr[warp];
    const int end   = g_rowptr[warp + 1];

    // pass 1: max
    float m = -INFINITY;
    for (int k = start + lane; k < end; k += 32) m = fmaxf(m, g_elog[k]);
#pragma unroll
    for (int o = 16; o; o >>= 1) m = fmaxf(m, __shfl_xor_sync(0xffffffffu, m, o));

    // pass 2: sum of exp
    float s = 0.f;
    for (int k = start + lane; k < end; k += 32) s += __expf(g_elog[k] - m);
#pragma unroll
    for (int o = 16; o; o >>= 1) s += __shfl_xor_sync(0xffffffffu, s, o);
    float inv = (s > 0.f) ? (1.f / s) : 0.f;

    // pass 3: weighted gather — each lane owns 4 output features
    float4 acc = make_float4(0.f, 0.f, 0.f, 0.f);
    for (int k = start; k < end; k++) {
        float c = __expf(g_elog[k] - m) * inv;
        int j = g_ccol[k];
        float4 v = *(const float4*)(g_seq + (size_t)j * OUTD + lane * 4);
        acc.x = fmaf(c, v.x, acc.x);
        acc.y = fmaf(c, v.y, acc.y);
        acc.z = fmaf(c, v.z, acc.z);
        acc.w = fmaf(c, v.w, acc.w);
    }

    float4 b = *(const float4*)(bias + lane * 4);
    acc.x += b.x; acc.y += b.y; acc.z += b.z; acc.w += b.w;
    acc.x = (acc.x > 0.f) ? acc.x : expm1f(acc.x);
    acc.y = (acc.y > 0.f) ? acc.y : expm1f(acc.y);
    acc.z = (acc.z > 0.f) ? acc.z : expm1f(acc.z);
    acc.w = (acc.w > 0.f) ? acc.w : expm1f(acc.w);
    *(float4*)(out + (size_t)warp * OUTD + lane * 4) = acc;
}

// ---------------- launch ----------------
extern "C" void kernel_launch(void* const* d_in, const int* in_sizes, int n_in,
                              void* d_out, int out_size) {
    const float* feat = (const float*)d_in[0];
    const float* W    = (const float*)d_in[1];
    const float* a_l  = (const float*)d_in[2];
    const float* b_l  = (const float*)d_in[3];
    const float* a_r  = (const float*)d_in[4];
    const float* b_r  = (const float*)d_in[5];
    const float* bias = (const float*)d_in[6];
    const int*   row  = (const int*)d_in[7];
    const int*   col  = (const int*)d_in[8];
    float* out = (float*)d_out;
    (void)in_sizes; (void)n_in; (void)out_size;

    zero_cnt_kernel<<<(NN + 255) / 256, 256>>>();
    prep_w_kernel<<<(IND * OUTD + 255) / 256, 256>>>(W);
    gemm_kernel<<<(NN + 127) / 128, 256>>>(feat);
    f12_kernel<<<(NN + 7) / 8, 256>>>(a_l, b_l, a_r, b_r);
    hist_kernel<<<(EE + 255) / 256, 256>>>(row);
    scanA_kernel<<<(NN + 1023) / 1024, 1024>>>();
    scanB_kernel<<<1, 128>>>();
    scanC_kernel<<<(NN + 1023) / 1024, 1024>>>();
    scatter_kernel<<<(EE + 255) / 256, 256>>>(row, col);
    row_kernel<<<(NN + 7) / 8, 256>>>(bias, out);
}